// round 5
// baseline (speedup 1.0000x reference)
#include <cuda_runtime.h>
#include <math.h>

#define BB   4
#define SS   512
#define HH   256
#define VV   32000
#define MM   (BB*SS)     // 2048

// ---------------- device scratch (no allocation anywhere) ----------------
__device__ float g_embT[HH * MM];           // [k][bt]               2 MB
__device__ float g_xp[(size_t)MM * 768];    // [bt][row]             6 MB
__device__ float g_hsR[(size_t)MM * HH];    // [bt][h] for GEMM      2 MB

// ---------------- kernel A: gather emb -> transposed ----------------------
__global__ void gather_kernel(const int* __restrict__ x,
                              const float* __restrict__ emb)
{
    const int bt  = blockIdx.x;
    const int tid = threadIdx.x;             // 0..63
    const int tok = x[bt];
    const float4 v = *(const float4*)(emb + (size_t)tok * HH + tid * 4);
    const int k = tid * 4;
    g_embT[(k + 0) * MM + bt] = v.x;
    g_embT[(k + 1) * MM + bt] = v.y;
    g_embT[(k + 2) * MM + bt] = v.z;
    g_embT[(k + 3) * MM + bt] = v.w;
}

// ---------------- kernel B: xp = emb @ W_ih^T + b_ih ----------------------
__global__ void __launch_bounds__(256) inproj_kernel(
    const float* __restrict__ W_ih, const float* __restrict__ b_ih)
{
    __shared__ float sW[16 * 256];
    const int r0 = blockIdx.y * 16;
    const int bt = blockIdx.x * 256 + threadIdx.x;
    for (int i = threadIdx.x; i < 16 * 256; i += 256)
        sW[i] = W_ih[(size_t)r0 * 256 + i];
    __syncthreads();

    float acc[16];
#pragma unroll
    for (int ri = 0; ri < 16; ri++) acc[ri] = 0.f;

#pragma unroll 4
    for (int k = 0; k < HH; k++) {
        const float e = g_embT[k * MM + bt];
#pragma unroll
        for (int ri = 0; ri < 16; ri++)
            acc[ri] += e * sW[ri * 256 + k];
    }
    float* o = g_xp + (size_t)bt * 768 + r0;
#pragma unroll
    for (int ri = 0; ri < 16; ri++)
        o[ri] = acc[ri] + b_ih[r0 + ri];
}

// ---------------- kernel C: GRU recurrence (cluster, f32x2, split barrier) -
// 4 clusters (1 per batch) x 8 CTAs x 384 threads.
// CTA rank owns hidden columns [rank*32, rank*32+32).
// Warp w (of 12): gate g = w>>2, k-chunk kc = w&3, lane = local column.
// W_hh slice lives in registers as packed f32x2; h broadcast via DSMEM.
__global__ void __launch_bounds__(384, 1) __cluster_dims__(8, 1, 1)
gru_kernel(const float* __restrict__ W_hh, const float* __restrict__ b_hh)
{
    __shared__ float  sh[2][HH];     // double-buffered h for this batch
    __shared__ float4 spart[96];     // partial dots [g*32 + col].kc

    const int tid  = threadIdx.x;
    const int w    = tid >> 5;       // 0..11
    const int lane = tid & 31;
    const int g    = w >> 2;         // gate 0..2
    const int kc   = w & 3;          // k-chunk 0..3
    unsigned rank;
    asm("mov.u32 %0, %%cluster_ctarank;" : "=r"(rank));
    const int batch = blockIdx.x >> 3;
    const int col   = (int)rank * 32 + lane;

    // persistent W_hh slice in registers, packed as f32x2 pairs
    unsigned long long wreg[32];
    {
        const ulonglong2* wp =
            (const ulonglong2*)(W_hh + (size_t)(g * HH + col) * HH + kc * 64);
#pragma unroll
        for (int i = 0; i < 16; i++) {
            const ulonglong2 wv = wp[i];
            wreg[2 * i + 0] = wv.x;
            wreg[2 * i + 1] = wv.y;
        }
    }

    float bhr = 0.f, bhz = 0.f, bhn = 0.f;
    int gcol = 0;
    if (tid < 32) {
        gcol = (int)rank * 32 + tid;
        bhr = b_hh[0 * HH + gcol];
        bhz = b_hh[1 * HH + gcol];
        bhn = b_hh[2 * HH + gcol];
    }

    const unsigned sh_addr = (unsigned)__cvta_generic_to_shared(&sh[0][0]);

    // init h0 = 0; first arrive pairs with the wait at t=1
    if (tid < HH) sh[0][tid] = 0.f;
    __syncthreads();
    asm volatile("barrier.cluster.arrive.aligned;" ::: "memory");

    for (int t = 1; t <= SS; t++) {
        const int cur = (t - 1) & 1;
        const int nxt = t & 1;

        // xp loads issued BEFORE the barrier wait (latency hidden)
        float xr = 0.f, xz = 0.f, xn = 0.f;
        if (tid < 32) {
            const size_t base = (size_t)(batch * SS + t - 1) * 768 + gcol;
            xr = g_xp[base + 0 * HH];
            xz = g_xp[base + 1 * HH];
            xn = g_xp[base + 2 * HH];
        }

        asm volatile("barrier.cluster.wait.aligned;" ::: "memory");

        // partial dot: packed f32x2, two accumulators
        {
            const float* hb = &sh[cur][kc * 64];
            unsigned long long a0 = 0ULL, a1 = 0ULL;
#pragma unroll
            for (int i = 0; i < 64; i += 8) {
                const ulonglong2 h0 = *(const ulonglong2*)(hb + i);
                const ulonglong2 h1 = *(const ulonglong2*)(hb + i + 4);
                asm("fma.rn.f32x2 %0, %1, %2, %0;"
                    : "+l"(a0) : "l"(wreg[i / 2 + 0]), "l"(h0.x));
                asm("fma.rn.f32x2 %0, %1, %2, %0;"
                    : "+l"(a1) : "l"(wreg[i / 2 + 1]), "l"(h0.y));
                asm("fma.rn.f32x2 %0, %1, %2, %0;"
                    : "+l"(a0) : "l"(wreg[i / 2 + 2]), "l"(h1.x));
                asm("fma.rn.f32x2 %0, %1, %2, %0;"
                    : "+l"(a1) : "l"(wreg[i / 2 + 3]), "l"(h1.y));
            }
            const float s = __uint_as_float((unsigned)(a0 & 0xffffffffu))
                          + __uint_as_float((unsigned)(a0 >> 32))
                          + __uint_as_float((unsigned)(a1 & 0xffffffffu))
                          + __uint_as_float((unsigned)(a1 >> 32));
            ((float*)&spart[g * 32 + lane])[kc] = s;
        }
        __syncthreads();

        if (tid < 32) {
            const float4 p0 = spart[0 * 32 + tid];
            const float4 p1 = spart[1 * 32 + tid];
            const float4 p2 = spart[2 * 32 + tid];
            const float hr = p0.x + p0.y + p0.z + p0.w + bhr;
            const float hz = p1.x + p1.y + p1.z + p1.w + bhz;
            const float hn = p2.x + p2.y + p2.z + p2.w + bhn;
            const float r  = 1.f / (1.f + __expf(-(xr + hr)));
            const float z  = 1.f / (1.f + __expf(-(xz + hz)));
            const float nv = xn + r * hn;
            const float n  = 1.f - 2.f / (__expf(2.f * nv) + 1.f);   // tanh
            const float ho = sh[cur][gcol];
            const float hnew = (1.f - z) * n + z * ho;

            // broadcast h_new into all 8 cluster CTAs' sh[nxt][gcol]
            const unsigned dst = sh_addr + (unsigned)(nxt * HH + gcol) * 4u;
#pragma unroll
            for (int rk = 0; rk < 8; rk++) {
                unsigned rem;
                asm volatile("mapa.shared::cluster.u32 %0, %1, %2;"
                             : "=r"(rem) : "r"(dst), "r"((unsigned)rk));
                asm volatile("st.shared::cluster.f32 [%0], %1;"
                             :: "r"(rem), "f"(hnew) : "memory");
            }
            g_hsR[(size_t)(batch * SS + t - 1) * HH + gcol] = hnew;
        }

        // release our stores; matching wait happens at top of next step
        asm volatile("barrier.cluster.arrive.aligned;" ::: "memory");
    }
    // consume the final arrive: no CTA exits while peer stores are in flight
    asm volatile("barrier.cluster.wait.aligned;" ::: "memory");
}

// ---------------- kernel D: output GEMM (TF32 mma, cp.async pipeline) -----
#define KC   16          // k-chunk
#define LDP  20          // padded smem row stride (floats)

__device__ __forceinline__ void cp16(unsigned smem_dst, const void* gsrc) {
    asm volatile("cp.async.cg.shared.global [%0], [%1], 16;"
                 :: "r"(smem_dst), "l"(gsrc) : "memory");
}

__global__ void __launch_bounds__(256, 2) gemm_out_kernel(
    const float* __restrict__ Wout, const float* __restrict__ bout,
    const int* __restrict__ x, float* __restrict__ out)
{
    __shared__ unsigned sA[2][128 * LDP];
    __shared__ unsigned sB[2][128 * LDP];

    const int m0   = blockIdx.y * 128;
    const int n0   = blockIdx.x * 128;
    const int tid  = threadIdx.x;
    const int lane = tid & 31;
    const int wid  = tid >> 5;          // 0..7
    const int wm   = wid & 3;           // 4 warps along m
    const int wn   = wid >> 2;          // 2 warps along n
    const int gid  = lane >> 2;
    const int tig  = lane & 3;

    float acc[2][8][4];
#pragma unroll
    for (int mi = 0; mi < 2; mi++)
#pragma unroll
        for (int ni = 0; ni < 8; ni++)
#pragma unroll
            for (int q = 0; q < 4; q++) acc[mi][ni][q] = 0.f;

    const int lrow = tid >> 2;
    const int lseg = (tid & 3) * 4;
    const unsigned sA0 = (unsigned)__cvta_generic_to_shared(&sA[0][0]);
    const unsigned sB0 = (unsigned)__cvta_generic_to_shared(&sB[0][0]);
    const unsigned stageBytes = 128 * LDP * 4;

    // prefetch chunk 0 into stage 0
#pragma unroll
    for (int p = 0; p < 2; p++) {
        const int row = p * 64 + lrow;
        cp16(sA0 + (unsigned)(row * LDP + lseg) * 4u,
             g_hsR + (size_t)(m0 + row) * HH + lseg);
        cp16(sB0 + (unsigned)(row * LDP + lseg) * 4u,
             Wout + (size_t)(n0 + row) * HH + lseg);
    }
    asm volatile("cp.async.commit_group;" ::: "memory");

    for (int c = 0; c < HH / KC; c++) {
        const int s = c & 1;
        if (c + 1 < HH / KC) {
            const unsigned so = (unsigned)((c + 1) & 1) * stageBytes;
            const int k0 = (c + 1) * KC;
#pragma unroll
            for (int p = 0; p < 2; p++) {
                const int row = p * 64 + lrow;
                cp16(sA0 + so + (unsigned)(row * LDP + lseg) * 4u,
                     g_hsR + (size_t)(m0 + row) * HH + k0 + lseg);
                cp16(sB0 + so + (unsigned)(row * LDP + lseg) * 4u,
                     Wout + (size_t)(n0 + row) * HH + k0 + lseg);
            }
            asm volatile("cp.async.commit_group;" ::: "memory");
            asm volatile("cp.async.wait_group 1;" ::: "memory");
        } else {
            asm volatile("cp.async.wait_group 0;" ::: "memory");
        }
        __syncthreads();

#pragma unroll
        for (int ks = 0; ks < 2; ks++) {
            const int k8 = ks * 8;
            unsigned af[2][4];
#pragma unroll
            for (int mi = 0; mi < 2; mi++) {
                const int base = wm * 32 + mi * 16;
                af[mi][0] = sA[s][(base + gid) * LDP + k8 + tig];
                af[mi][1] = sA[s][(base + gid + 8) * LDP + k8 + tig];
                af[mi][2] = sA[s][(base + gid) * LDP + k8 + tig + 4];
                af[mi][3] = sA[s][(base + gid + 8) * LDP + k8 + tig + 4];
            }
#pragma unroll
            for (int ni = 0; ni < 8; ni++) {
                const int nb = wn * 64 + ni * 8;
                const unsigned b0 = sB[s][(nb + gid) * LDP + k8 + tig];
                const unsigned b1 = sB[s][(nb + gid) * LDP + k8 + tig + 4];
#pragma unroll
                for (int mi = 0; mi < 2; mi++) {
                    asm volatile(
                        "mma.sync.aligned.m16n8k8.row.col.f32.tf32.tf32.f32 "
                        "{%0,%1,%2,%3}, {%4,%5,%6,%7}, {%8,%9}, {%0,%1,%2,%3};"
                        : "+f"(acc[mi][ni][0]), "+f"(acc[mi][ni][1]),
                          "+f"(acc[mi][ni][2]), "+f"(acc[mi][ni][3])
                        : "r"(af[mi][0]), "r"(af[mi][1]), "r"(af[mi][2]), "r"(af[mi][3]),
                          "r"(b0), "r"(b1));
                }
            }
        }
        __syncthreads();
    }

    // epilogue: bias + symbolic mask + store
#pragma unroll
    for (int mi = 0; mi < 2; mi++) {
        const int rbase = m0 + wm * 32 + mi * 16;
#pragma unroll
        for (int half = 0; half < 2; half++) {
            const int row = rbase + gid + half * 8;    // bt
            const int t   = row & (SS - 1);
            const bool pz = (t > 0) && (x[row - 1] == 0);
#pragma unroll
            for (int ni = 0; ni < 8; ni++) {
                const int col = n0 + wn * 64 + ni * 8 + tig * 2;
                float v0 = acc[mi][ni][half * 2 + 0] + bout[col];
                float v1 = acc[mi][ni][half * 2 + 1] + bout[col + 1];
                if (pz) {
                    if (col >= 3)     v0 = -INFINITY;
                    if (col + 1 >= 3) v1 = -INFINITY;
                }
                *(float2*)(out + (size_t)row * VV + col) = make_float2(v0, v1);
            }
        }
    }
}

// ---------------- launch ---------------------------------------------------
extern "C" void kernel_launch(void* const* d_in, const int* in_sizes, int n_in,
                              void* d_out, int out_size)
{
    const int*   x     = (const int*)  d_in[0];
    const float* emb   = (const float*)d_in[1];
    const float* W_ih  = (const float*)d_in[2];
    const float* W_hh  = (const float*)d_in[3];
    const float* b_ih  = (const float*)d_in[4];
    const float* b_hh  = (const float*)d_in[5];
    const float* W_out = (const float*)d_in[6];
    const float* b_out = (const float*)d_in[7];
    float* out = (float*)d_out;

    gather_kernel<<<MM, 64>>>(x, emb);
    inproj_kernel<<<dim3(MM / 256, 768 / 16), 256>>>(W_ih, b_ih);
    gru_kernel<<<32, 384>>>(W_hh, b_hh);
    gemm_out_kernel<<<dim3(VV / 128, MM / 128), 256>>>(W_out, b_out, x, out);
}